// round 2
// baseline (speedup 1.0000x reference)
#include <cuda_runtime.h>
#include <cstdint>

// QuantumCircuitSimulator2: 24 qubits, 8 steps of 4-qubit (16x16 complex) gates.
// State layout: float32 [2, 2^24] (re plane, im plane). Qubit q = bit q of index.
// Gate step: new[j] = sum_k (gr[j,k] + i*gi[j,k]) * old[k], where gate index bit t
// corresponds to qubit targets[step][t].

#define NQ 24
#define NSTATE (1u << NQ)
#define NGROUPS (1u << (NQ - 4))   // 2^20 groups of 16 amplitudes
#define NSTEPS 8

// ---- packed f32x2 helpers (Blackwell FFMA2 path) ----
__device__ __forceinline__ unsigned long long fma2(unsigned long long a,
                                                   unsigned long long b,
                                                   unsigned long long c) {
    unsigned long long d;
    asm("fma.rn.f32x2 %0, %1, %2, %3;" : "=l"(d) : "l"(a), "l"(b), "l"(c));
    return d;
}
__device__ __forceinline__ unsigned long long pack2(float lo, float hi) {
    unsigned long long d;
    asm("mov.b64 %0, {%1, %2};" : "=l"(d) : "f"(lo), "f"(hi));
    return d;
}
__device__ __forceinline__ void unpack2(unsigned long long v, float& lo, float& hi) {
    asm("mov.b64 {%0, %1}, %2;" : "=f"(lo), "=f"(hi) : "l"(v));
}

__global__ __launch_bounds__(256)
void qstep_kernel(const float* __restrict__ src,
                  float* __restrict__ dst,
                  const float* __restrict__ gates,
                  const int* __restrict__ targets_raw,
                  int step) {
    // Karatsuba gate tables: A = gr, B = gr+gi, C = gi-gr  (each 16x16)
    __shared__ __align__(16) float sG[3 * 256];

    const float* g = gates + (size_t)step * 512;  // [2,16,16] for this step
    for (int i = threadIdx.x; i < 768; i += 256) {
        int t = i >> 8;
        int idx = i & 255;
        float gr = g[idx];
        float gi = g[256 + idx];
        sG[i] = (t == 0) ? gr : ((t == 1) ? (gr + gi) : (gi - gr));
    }

    // Target dtype detection: if the buffer holds int64 values (< 24), every
    // odd 32-bit word is zero. If it holds int32, words 1 and 3 are
    // targets[0][1] and targets[0][3], which are distinct (can't both be 0).
    int stride = (targets_raw[1] == 0 && targets_raw[3] == 0) ? 2 : 1;
    int q0 = targets_raw[(step * 4 + 0) * stride];
    int q1 = targets_raw[(step * 4 + 1) * stride];
    int q2 = targets_raw[(step * 4 + 2) * stride];
    int q3 = targets_raw[(step * 4 + 3) * stride];
    unsigned m0 = 1u << q0, m1 = 1u << q1, m2 = 1u << q2, m3 = 1u << q3;

    // Sorted copy for zero-bit insertion (ascending)
    int a = q0, b = q1, c = q2, d = q3, t;
    if (a > b) { t = a; a = b; b = t; }
    if (c > d) { t = c; c = d; d = t; }
    if (a > c) { t = a; a = c; c = t; }
    if (b > d) { t = b; b = d; d = t; }
    if (b > c) { t = b; b = c; c = t; }

    __syncthreads();

    unsigned g20 = blockIdx.x * 256u + threadIdx.x;
    // Insert zero bits at sorted target positions (ascending insert is stable)
    unsigned base = g20;
    base = ((base >> a) << (a + 1)) | (base & ((1u << a) - 1u));
    base = ((base >> b) << (b + 1)) | (base & ((1u << b) - 1u));
    base = ((base >> c) << (c + 1)) | (base & ((1u << c) - 1u));
    base = ((base >> d) << (d + 1)) | (base & ((1u << d) - 1u));

    const float* __restrict__ srcRe = src;
    const float* __restrict__ srcIm = src + NSTATE;

    // Gather the 16 amplitudes of this group
    float sr[16], si[16];
    unsigned off[16];
#pragma unroll
    for (int j = 0; j < 16; j++) {
        unsigned o = ((j & 1) ? m0 : 0u) | ((j & 2) ? m1 : 0u) |
                     ((j & 4) ? m2 : 0u) | ((j & 8) ? m3 : 0u);
        off[j] = o;
        sr[j] = srcRe[base + o];
        si[j] = srcIm[base + o];
    }

    // Pack along k into f32x2 pairs; u = sr + si
    unsigned long long sr2[8], si2[8], u2[8];
#pragma unroll
    for (int kk = 0; kk < 8; kk++) {
        sr2[kk] = pack2(sr[2 * kk], sr[2 * kk + 1]);
        si2[kk] = pack2(si[2 * kk], si[2 * kk + 1]);
        u2[kk]  = pack2(sr[2 * kk] + si[2 * kk], sr[2 * kk + 1] + si[2 * kk + 1]);
    }

    float* __restrict__ dstRe = dst;
    float* __restrict__ dstIm = dst + NSTATE;

#pragma unroll
    for (int j = 0; j < 16; j++) {
        const unsigned long long* Aj =
            reinterpret_cast<const unsigned long long*>(sG + j * 16);
        const unsigned long long* Bj =
            reinterpret_cast<const unsigned long long*>(sG + 256 + j * 16);
        const unsigned long long* Cj =
            reinterpret_cast<const unsigned long long*>(sG + 512 + j * 16);
        unsigned long long a1 = 0ull, a2 = 0ull, a3 = 0ull;
#pragma unroll
        for (int kk = 0; kk < 8; kk++) {
            a1 = fma2(Aj[kk], u2[kk], a1);   // sum gr*(sr+si)
            a2 = fma2(Bj[kk], si2[kk], a2);  // sum (gr+gi)*si
            a3 = fma2(Cj[kk], sr2[kk], a3);  // sum (gi-gr)*sr
        }
        float lo, hi, t1, t2, t3;
        unpack2(a1, lo, hi); t1 = lo + hi;
        unpack2(a2, lo, hi); t2 = lo + hi;
        unpack2(a3, lo, hi); t3 = lo + hi;
        unsigned o = base + off[j];
        dstRe[o] = t1 - t2;  // re = gr*sr - gi*si
        dstIm[o] = t1 + t3;  // im = gr*si + gi*sr
    }
}

extern "C" void kernel_launch(void* const* d_in, const int* in_sizes, int n_in,
                              void* d_out, int out_size) {
    const float* state   = (const float*)d_in[0];
    const int*   targets = (const int*)d_in[1];
    const float* gates   = (const float*)d_in[2];
    float*       out     = (float*)d_out;

    dim3 block(256);
    dim3 grid(NGROUPS / 256);  // 4096 blocks

    // Step 0: read input, write output. Steps 1..7: in-place on d_out
    // (each thread owns its 16-amplitude group -> race-free in-place).
    qstep_kernel<<<grid, block>>>(state, out, gates, targets, 0);
    for (int s = 1; s < NSTEPS; s++) {
        qstep_kernel<<<grid, block>>>(out, out, gates, targets, s);
    }
}